// round 1
// baseline (speedup 1.0000x reference)
#include <cuda_runtime.h>
#include <math.h>

#define B_ 4
#define T_ 2048
#define D_ 1024
#define E_ 8
#define K_ 2
#define F_ 4096
#define N_ (B_*T_)            // 8192 tokens

// ---------------- scratch (device globals; no runtime allocation) ----------
__device__ int   g_cnt[E_];
__device__ int   g_off[E_];
__device__ int   g_tok[E_*N_];
__device__ float g_gate[E_*N_];
// h buffer: N*K rows x F cols, fp32 = 268 MB (BSS, allowed)
__device__ float g_h[(long long)N_*K_*F_];

// ---------------- kernel 0: zero per-expert counters ------------------------
__global__ void init_kernel() {
    if (threadIdx.x < E_) g_cnt[threadIdx.x] = 0;
}

// ---------------- kernel 1: gating (logits, top-2, softmax, bucket assign) --
__global__ void gate_kernel(const float* __restrict__ x,
                            const float* __restrict__ gw) {
    int gtid = blockIdx.x * blockDim.x + threadIdx.x;
    int t    = gtid >> 5;
    int lane = gtid & 31;
    if (t >= N_) return;

    const float* xr = x + (size_t)t * D_;
    float acc[E_];
    #pragma unroll
    for (int e = 0; e < E_; e++) acc[e] = 0.f;

    for (int d = lane; d < D_; d += 32) {
        float xv = xr[d];
        #pragma unroll
        for (int e = 0; e < E_; e++)
            acc[e] = fmaf(xv, gw[d * E_ + e], acc[e]);
    }
    #pragma unroll
    for (int e = 0; e < E_; e++) {
        #pragma unroll
        for (int o = 16; o > 0; o >>= 1)
            acc[e] += __shfl_xor_sync(0xffffffffu, acc[e], o);
    }

    if (lane == 0) {
        // top-2 (first occurrence wins on ties, matching jax top_k)
        int i0 = 0; float v0 = acc[0];
        #pragma unroll
        for (int e = 1; e < E_; e++) if (acc[e] > v0) { v0 = acc[e]; i0 = e; }
        int i1 = -1; float v1 = -1e30f;
        #pragma unroll
        for (int e = 0; e < E_; e++)
            if (e != i0 && acc[e] > v1) { v1 = acc[e]; i1 = e; }

        // softmax over the two top values (v0 >= v1)
        float e1  = expf(v1 - v0);
        float inv = 1.f / (1.f + e1);
        float g0 = inv, g1 = e1 * inv;

        int p0 = atomicAdd(&g_cnt[i0], 1);
        g_tok[i0 * N_ + p0]  = t;
        g_gate[i0 * N_ + p0] = g0;
        int p1 = atomicAdd(&g_cnt[i1], 1);
        g_tok[i1 * N_ + p1]  = t;
        g_gate[i1 * N_ + p1] = g1;
    }
}

// ---------------- kernel 2: tiny exclusive scan of counts -------------------
__global__ void scan_kernel() {
    int o = 0;
    for (int e = 0; e < E_; e++) { g_off[e] = o; o += g_cnt[e]; }
}

// ---------------- GEMM config ----------------------------------------------
#define BM 128
#define BN 128
#define BKK 8
#define TM 8
#define TN 8
// 256 threads per block, 8x8 micro-tile, double-buffered smem

__device__ __forceinline__ float gelu_f(float v) {
    return 0.5f * v * (1.f + erff(v * 0.70710678118654752440f));
}

// ---------------- kernel 3: h = gelu(gather(x) @ w1[e] + b1[e]) -------------
__global__ __launch_bounds__(256, 2)
void gemm1_kernel(const float* __restrict__ x,
                  const float* __restrict__ w1,
                  const float* __restrict__ b1) {
    int e   = blockIdx.z;
    int cnt = g_cnt[e];
    int m0  = blockIdx.y * BM;
    if (m0 >= cnt) return;
    int n0  = blockIdx.x * BN;
    int off = g_off[e];

    __shared__ float As[2][BKK][BM + 4];
    __shared__ float Bs[2][BKK][BN];

    int tid  = threadIdx.x;
    int arow = tid >> 1;
    int ak   = (tid & 1) << 2;
    int grow = m0 + arow;
    bool avalid = grow < cnt;
    const float* xrow = avalid ? (x + (size_t)g_tok[e * N_ + grow] * D_) : x;

    int bk = tid >> 5;
    int bn = (tid & 31) << 2;
    const float* wbase = w1 + (size_t)e * D_ * F_ + n0 + bn;

    int tx = tid & 15, ty = tid >> 4;

    float acc[TM][TN];
    #pragma unroll
    for (int i = 0; i < TM; i++)
        #pragma unroll
        for (int j = 0; j < TN; j++) acc[i][j] = 0.f;

    float4 z4 = make_float4(0.f, 0.f, 0.f, 0.f);

    { // preload tile 0
        float4 av = avalid ? *(const float4*)(xrow + ak) : z4;
        As[0][ak + 0][arow] = av.x; As[0][ak + 1][arow] = av.y;
        As[0][ak + 2][arow] = av.z; As[0][ak + 3][arow] = av.w;
        *(float4*)&Bs[0][bk][bn] = *(const float4*)(wbase + (size_t)bk * F_);
    }
    __syncthreads();

    const int KT = D_ / BKK;   // 128
    int buf = 0;
    for (int kt = 0; kt < KT; ++kt) {
        float4 aReg = z4, bReg = z4;
        if (kt + 1 < KT) {
            int kg = (kt + 1) * BKK;
            if (avalid) aReg = *(const float4*)(xrow + kg + ak);
            bReg = *(const float4*)(wbase + (size_t)(kg + bk) * F_);
        }
        #pragma unroll
        for (int kk = 0; kk < BKK; kk++) {
            float4 a0 = *(const float4*)&As[buf][kk][ty * TM];
            float4 a1 = *(const float4*)&As[buf][kk][ty * TM + 4];
            float4 b0 = *(const float4*)&Bs[buf][kk][tx * TN];
            float4 b1v = *(const float4*)&Bs[buf][kk][tx * TN + 4];
            float a[TM] = {a0.x, a0.y, a0.z, a0.w, a1.x, a1.y, a1.z, a1.w};
            float b[TN] = {b0.x, b0.y, b0.z, b0.w, b1v.x, b1v.y, b1v.z, b1v.w};
            #pragma unroll
            for (int i = 0; i < TM; i++)
                #pragma unroll
                for (int j = 0; j < TN; j++)
                    acc[i][j] = fmaf(a[i], b[j], acc[i][j]);
        }
        if (kt + 1 < KT) {
            int nb = buf ^ 1;
            As[nb][ak + 0][arow] = aReg.x; As[nb][ak + 1][arow] = aReg.y;
            As[nb][ak + 2][arow] = aReg.z; As[nb][ak + 3][arow] = aReg.w;
            *(float4*)&Bs[nb][bk][bn] = bReg;
            __syncthreads();
            buf = nb;
        }
    }

    // epilogue: bias + exact gelu -> g_h
    #pragma unroll
    for (int i = 0; i < TM; i++) {
        int r = m0 + ty * TM + i;
        if (r >= cnt) break;
        float*       hrow = g_h + (size_t)(off + r) * F_ + n0 + tx * TN;
        const float* brow = b1 + (size_t)e * F_ + n0 + tx * TN;
        float4 v0, v1;
        v0.x = gelu_f(acc[i][0] + brow[0]);
        v0.y = gelu_f(acc[i][1] + brow[1]);
        v0.z = gelu_f(acc[i][2] + brow[2]);
        v0.w = gelu_f(acc[i][3] + brow[3]);
        v1.x = gelu_f(acc[i][4] + brow[4]);
        v1.y = gelu_f(acc[i][5] + brow[5]);
        v1.z = gelu_f(acc[i][6] + brow[6]);
        v1.w = gelu_f(acc[i][7] + brow[7]);
        *(float4*)hrow       = v0;
        *((float4*)hrow + 1) = v1;
    }
}

// ---------------- kernel 4: out += gate * (h @ w2[e] + b2[e]) ---------------
__global__ __launch_bounds__(256, 2)
void gemm2_kernel(const float* __restrict__ w2,
                  const float* __restrict__ b2,
                  float* __restrict__ out) {
    int e   = blockIdx.z;
    int cnt = g_cnt[e];
    int m0  = blockIdx.y * BM;
    if (m0 >= cnt) return;
    int n0  = blockIdx.x * BN;
    int off = g_off[e];

    __shared__ float As[2][BKK][BM + 4];
    __shared__ float Bs[2][BKK][BN];

    int tid  = threadIdx.x;
    int arow = tid >> 1;
    int ak   = (tid & 1) << 2;
    int grow = m0 + arow;
    bool avalid = grow < cnt;
    const float* hrow = g_h + (size_t)(off + (avalid ? grow : 0)) * F_;

    int bk = tid >> 5;
    int bn = (tid & 31) << 2;
    const float* wbase = w2 + (size_t)e * F_ * D_ + n0 + bn;

    int tx = tid & 15, ty = tid >> 4;

    float acc[TM][TN];
    #pragma unroll
    for (int i = 0; i < TM; i++)
        #pragma unroll
        for (int j = 0; j < TN; j++) acc[i][j] = 0.f;

    float4 z4 = make_float4(0.f, 0.f, 0.f, 0.f);

    { // preload tile 0
        float4 av = avalid ? *(const float4*)(hrow + ak) : z4;
        As[0][ak + 0][arow] = av.x; As[0][ak + 1][arow] = av.y;
        As[0][ak + 2][arow] = av.z; As[0][ak + 3][arow] = av.w;
        *(float4*)&Bs[0][bk][bn] = *(const float4*)(wbase + (size_t)bk * D_);
    }
    __syncthreads();

    const int KT = F_ / BKK;   // 512
    int buf = 0;
    for (int kt = 0; kt < KT; ++kt) {
        float4 aReg = z4, bReg = z4;
        if (kt + 1 < KT) {
            int kg = (kt + 1) * BKK;
            if (avalid) aReg = *(const float4*)(hrow + kg + ak);
            bReg = *(const float4*)(wbase + (size_t)(kg + bk) * D_);
        }
        #pragma unroll
        for (int kk = 0; kk < BKK; kk++) {
            float4 a0 = *(const float4*)&As[buf][kk][ty * TM];
            float4 a1 = *(const float4*)&As[buf][kk][ty * TM + 4];
            float4 b0 = *(const float4*)&Bs[buf][kk][tx * TN];
            float4 b1v = *(const float4*)&Bs[buf][kk][tx * TN + 4];
            float a[TM] = {a0.x, a0.y, a0.z, a0.w, a1.x, a1.y, a1.z, a1.w};
            float b[TN] = {b0.x, b0.y, b0.z, b0.w, b1v.x, b1v.y, b1v.z, b1v.w};
            #pragma unroll
            for (int i = 0; i < TM; i++)
                #pragma unroll
                for (int j = 0; j < TN; j++)
                    acc[i][j] = fmaf(a[i], b[j], acc[i][j]);
        }
        if (kt + 1 < KT) {
            int nb = buf ^ 1;
            As[nb][ak + 0][arow] = aReg.x; As[nb][ak + 1][arow] = aReg.y;
            As[nb][ak + 2][arow] = aReg.z; As[nb][ak + 3][arow] = aReg.w;
            *(float4*)&Bs[nb][bk][bn] = bReg;
            __syncthreads();
            buf = nb;
        }
    }

    // epilogue: bias, gate scale, scatter-add to token rows.
    // Each (token, col) receives exactly 2 adds (K=2) -> fp32 commutative,
    // bitwise deterministic regardless of atomic ordering.
    #pragma unroll
    for (int i = 0; i < TM; i++) {
        int r = m0 + ty * TM + i;
        if (r >= cnt) break;
        int   tok = g_tok[e * N_ + r];
        float g   = g_gate[e * N_ + r];
        float*       orow = out + (size_t)tok * D_ + n0 + tx * TN;
        const float* brow = b2 + (size_t)e * D_ + n0 + tx * TN;
        #pragma unroll
        for (int j = 0; j < TN; j++)
            atomicAdd(&orow[j], g * (acc[i][j] + brow[j]));
    }
}

// ---------------- launch -----------------------------------------------------
extern "C" void kernel_launch(void* const* d_in, const int* in_sizes, int n_in,
                              void* d_out, int out_size) {
    const float* x  = (const float*)d_in[0];
    const float* gw = (const float*)d_in[1];
    const float* w1 = (const float*)d_in[2];
    const float* b1 = (const float*)d_in[3];
    const float* w2 = (const float*)d_in[4];
    const float* b2 = (const float*)d_in[5];
    float* out = (float*)d_out;

    cudaMemsetAsync(out, 0, (size_t)out_size * sizeof(float), 0);
    init_kernel<<<1, 32>>>();
    gate_kernel<<<(N_ * 32) / 256, 256>>>(x, gw);
    scan_kernel<<<1, 1>>>();

    dim3 g1(F_ / BN, N_ / BM, E_);   // (32, 64, 8), cnt-guarded
    gemm1_kernel<<<g1, 256>>>(x, w1, b1);

    dim3 g2(D_ / BN, N_ / BM, E_);   // (8, 64, 8), cnt-guarded
    gemm2_kernel<<<g2, 256>>>(w2, b2, out);
}

// round 3
// speedup vs baseline: 3.1442x; 3.1442x over previous
#include <cuda_runtime.h>
#include <cuda_fp16.h>
#include <math.h>
#include <stdint.h>

#define B_ 4
#define T_ 2048
#define D_ 1024
#define E_ 8
#define F_ 4096
#define N_ (B_*T_)            // 8192 tokens

// ---- GEMM tile config ----
#define BM 128
#define BN 128
#define BK 64                 // fp16 elems per k-tile (128 B rows)
#define STAGES 3
#define NTHREADS 256

// smem layout per stage (bytes)
#define OFF_AH 0
#define OFF_AL 16384
#define OFF_BH 32768
#define OFF_BL 49152
#define STAGE_BYTES 65536
#define SMEM_TOTAL (STAGES*STAGE_BYTES)    // 196608

// ---------------- device scratch ---------------------------------------------
__device__ int    g_cnt[E_];
__device__ int    g_off[E_];
__device__ int    g_tok[E_*N_];
__device__ float  g_gate[E_*N_];
__device__ __half g_x_hi[(size_t)N_*D_];
__device__ __half g_x_lo[(size_t)N_*D_];
__device__ __half g_w1t_hi[(size_t)E_*F_*D_];   // [E][F][D] K-major
__device__ __half g_w1t_lo[(size_t)E_*F_*D_];
__device__ __half g_w2t_hi[(size_t)E_*D_*F_];   // [E][D][F] K-major
__device__ __half g_w2t_lo[(size_t)E_*D_*F_];
__device__ __half g_h_hi[(size_t)N_*2*F_];      // [N*K][F]
__device__ __half g_h_lo[(size_t)N_*2*F_];

// ---------------- helpers -----------------------------------------------------
__device__ __forceinline__ uint32_t smem_u32(const void* p) {
    uint32_t a;
    asm("{ .reg .u64 t; cvta.to.shared.u64 t, %1; cvt.u32.u64 %0, t; }"
        : "=r"(a) : "l"(p));
    return a;
}
__device__ __forceinline__ void cp16(uint32_t dst, const void* src) {
    asm volatile("cp.async.cg.shared.global [%0], [%1], 16;"
                 :: "r"(dst), "l"(src) : "memory");
}
__device__ __forceinline__ void cp_commit() {
    asm volatile("cp.async.commit_group;" ::: "memory");
}
template<int NN>
__device__ __forceinline__ void cp_wait() {
    asm volatile("cp.async.wait_group %0;" :: "n"(NN) : "memory");
}
__device__ __forceinline__ void ldm4(uint32_t& r0, uint32_t& r1,
                                     uint32_t& r2, uint32_t& r3, uint32_t a) {
    asm volatile("ldmatrix.sync.aligned.m8n8.x4.shared.b16 {%0,%1,%2,%3}, [%4];"
                 : "=r"(r0), "=r"(r1), "=r"(r2), "=r"(r3) : "r"(a));
}
__device__ __forceinline__ void mma16816(float* c, const uint32_t* a,
                                         uint32_t b0, uint32_t b1) {
    asm volatile(
        "mma.sync.aligned.m16n8k16.row.col.f32.f16.f16.f32 "
        "{%0,%1,%2,%3}, {%4,%5,%6,%7}, {%8,%9}, {%0,%1,%2,%3};"
        : "+f"(c[0]), "+f"(c[1]), "+f"(c[2]), "+f"(c[3])
        : "r"(a[0]), "r"(a[1]), "r"(a[2]), "r"(a[3]), "r"(b0), "r"(b1));
}
__device__ __forceinline__ void split_h(float v, __half& h, __half& l) {
    h = __float2half_rn(v);
    l = __float2half_rn(v - __half2float(h));
}
__device__ __forceinline__ uint32_t pack2(__half a, __half b) {
    return (uint32_t)__half_as_ushort(a) | ((uint32_t)__half_as_ushort(b) << 16);
}
__device__ __forceinline__ float gelu_f(float v) {
    return 0.5f * v * (1.f + erff(v * 0.70710678118654752440f));
}

// ---------------- small kernels ------------------------------------------------
__global__ void init_kernel() { if (threadIdx.x < E_) g_cnt[threadIdx.x] = 0; }

__global__ void gate_kernel(const float* __restrict__ x,
                            const float* __restrict__ gw) {
    int gtid = blockIdx.x * blockDim.x + threadIdx.x;
    int t = gtid >> 5, lane = gtid & 31;
    if (t >= N_) return;
    const float* xr = x + (size_t)t * D_;
    float acc[E_];
    #pragma unroll
    for (int e = 0; e < E_; e++) acc[e] = 0.f;
    for (int d = lane; d < D_; d += 32) {
        float xv = xr[d];
        #pragma unroll
        for (int e = 0; e < E_; e++) acc[e] = fmaf(xv, gw[d * E_ + e], acc[e]);
    }
    #pragma unroll
    for (int e = 0; e < E_; e++)
        #pragma unroll
        for (int o = 16; o > 0; o >>= 1)
            acc[e] += __shfl_xor_sync(0xffffffffu, acc[e], o);
    if (lane == 0) {
        int i0 = 0; float v0 = acc[0];
        #pragma unroll
        for (int e = 1; e < E_; e++) if (acc[e] > v0) { v0 = acc[e]; i0 = e; }
        int i1 = -1; float v1 = -1e30f;
        #pragma unroll
        for (int e = 0; e < E_; e++) if (e != i0 && acc[e] > v1) { v1 = acc[e]; i1 = e; }
        float e1 = expf(v1 - v0), inv = 1.f / (1.f + e1);
        int p0 = atomicAdd(&g_cnt[i0], 1);
        g_tok[i0 * N_ + p0] = t;  g_gate[i0 * N_ + p0] = inv;
        int p1 = atomicAdd(&g_cnt[i1], 1);
        g_tok[i1 * N_ + p1] = t;  g_gate[i1 * N_ + p1] = e1 * inv;
    }
}

__global__ void scan_kernel() {
    int o = 0;
    for (int e = 0; e < E_; e++) { g_off[e] = o; o += g_cnt[e]; }
}

__global__ void prep_x_kernel(const float* __restrict__ x) {
    size_t i4 = (size_t)blockIdx.x * blockDim.x + threadIdx.x;
    float4 v = ((const float4*)x)[i4];
    __half h0,h1,h2,h3,l0,l1,l2,l3;
    split_h(v.x, h0, l0); split_h(v.y, h1, l1);
    split_h(v.z, h2, l2); split_h(v.w, h3, l3);
    ((uint2*)g_x_hi)[i4] = make_uint2(pack2(h0,h1), pack2(h2,h3));
    ((uint2*)g_x_lo)[i4] = make_uint2(pack2(l0,l1), pack2(l2,l3));
}

// transpose + split: in [E][RIN][CIN] fp32 -> out [E][CIN][RIN] fp16 hi/lo
template<int W>
__global__ void prep_w_kernel(const float* __restrict__ w) {
    constexpr int RIN = (W == 1) ? D_ : F_;
    constexpr int CIN = (W == 1) ? F_ : D_;
    __half* whi = (W == 1) ? g_w1t_hi : g_w2t_hi;
    __half* wlo = (W == 1) ? g_w1t_lo : g_w2t_lo;
    __shared__ float tile[32][33];
    int e = blockIdx.z;
    int c0 = blockIdx.x * 32, r0 = blockIdx.y * 32;
    int tx = threadIdx.x, ty = threadIdx.y;     // (32, 8)
    const float* wi = w + (size_t)e * RIN * CIN;
    #pragma unroll
    for (int i = 0; i < 4; i++)
        tile[ty + 8*i][tx] = wi[(size_t)(r0 + ty + 8*i) * CIN + c0 + tx];
    __syncthreads();
    size_t ob = (size_t)e * CIN * RIN;
    #pragma unroll
    for (int i = 0; i < 4; i++) {
        int c = c0 + ty + 8*i, r = r0 + tx;
        __half h, l;
        split_h(tile[tx][ty + 8*i], h, l);
        whi[ob + (size_t)c * RIN + r] = h;
        wlo[ob + (size_t)c * RIN + r] = l;
    }
}

// ---------------- grouped GEMM on HMMA (fp16 3-term split) -------------------
// PHASE 1: h = gelu(gather(x) @ w1t[e]^T + b1[e])
// PHASE 2: out += gate * (h @ w2t[e]^T + b2[e])
template<int PHASE>
__global__ __launch_bounds__(NTHREADS, 1)
void moe_gemm_kernel(const float* __restrict__ bias_g, float* __restrict__ out) {
    constexpr int KT    = (PHASE == 1) ? D_ : F_;
    constexpr int KT64  = KT / BK;
    constexpr int NFULL = (PHASE == 1) ? F_ : D_;

    int e   = blockIdx.z;
    int cnt = g_cnt[e];
    int m0  = blockIdx.y * BM;
    if (m0 >= cnt) return;
    int n0  = blockIdx.x * BN;
    int off = g_off[e];

    extern __shared__ __align__(1024) char smem[];
    uint32_t sb = smem_u32(smem);
    int tid = threadIdx.x, wid = tid >> 5, lane = tid & 31;

    const __half* Ah = (PHASE == 1) ? g_x_hi : g_h_hi;
    const __half* Al = (PHASE == 1) ? g_x_lo : g_h_lo;
    const __half* Bh = ((PHASE == 1) ? g_w1t_hi : g_w2t_hi) + (size_t)e * (size_t)NFULL * KT;
    const __half* Bl = ((PHASE == 1) ? g_w1t_lo : g_w2t_lo) + (size_t)e * (size_t)NFULL * KT;

    // ---- per-thread cp.async setup: 4 rows per tile, fixed chunk = tid&7 ----
    int rbase = tid >> 3;
    int csw   = (tid & 7) ^ (rbase & 7);
    const __half *a_h[4], *a_l[4], *b_h[4], *b_l[4];
    uint32_t dstoff[4];
    #pragma unroll
    for (int i = 0; i < 4; i++) {
        int r = rbase + 32 * i;
        dstoff[i] = (uint32_t)(r * 128 + csw * 16);
        int grow = min(m0 + r, cnt - 1);
        size_t arow = (PHASE == 1) ? (size_t)g_tok[e * N_ + grow]
                                   : (size_t)(off + grow);
        a_h[i] = Ah + arow * KT + (tid & 7) * 8;
        a_l[i] = Al + arow * KT + (tid & 7) * 8;
        size_t brow = (size_t)(n0 + r);
        b_h[i] = Bh + brow * KT + (tid & 7) * 8;
        b_l[i] = Bl + brow * KT + (tid & 7) * 8;
    }

    auto load_stage = [&](int kt, int slot) {
        uint32_t s0 = sb + slot * STAGE_BYTES;
        int koff = kt * BK;
        #pragma unroll
        for (int i = 0; i < 4; i++) {
            cp16(s0 + OFF_AH + dstoff[i], a_h[i] + koff);
            cp16(s0 + OFF_AL + dstoff[i], a_l[i] + koff);
            cp16(s0 + OFF_BH + dstoff[i], b_h[i] + koff);
            cp16(s0 + OFF_BL + dstoff[i], b_l[i] + koff);
        }
    };

    // ---- fragment address constants ----
    int m_warp = (wid & 3) * 32;
    int n_warp = (wid >> 2) * 64;
    uint32_t a_rowb[2], b_rowb[4];
    #pragma unroll
    for (int f = 0; f < 2; f++)
        a_rowb[f] = (uint32_t)((m_warp + f * 16 + (lane & 15)) * 128);
    #pragma unroll
    for (int q = 0; q < 4; q++)
        b_rowb[q] = (uint32_t)((n_warp + q * 16 + ((lane & 16) >> 1) + (lane & 7)) * 128);
    uint32_t a_chsel = (uint32_t)(lane >> 4);
    uint32_t b_chsel = (uint32_t)((lane >> 3) & 1);
    uint32_t lxor    = (uint32_t)(lane & 7);

    float acc[2][8][4];
    #pragma unroll
    for (int mf = 0; mf < 2; mf++)
        #pragma unroll
        for (int nb = 0; nb < 8; nb++)
            #pragma unroll
            for (int i = 0; i < 4; i++) acc[mf][nb][i] = 0.f;

    // ---- prologue ----
    load_stage(0, 0); cp_commit();
    if (KT64 > 1) load_stage(1, 1);
    cp_commit();

    // ---- main loop ----
    for (int kt = 0; kt < KT64; kt++) {
        cp_wait<1>();
        __syncthreads();
        if (kt + 2 < KT64) load_stage(kt + 2, (kt + 2) % STAGES);
        cp_commit();

        uint32_t s0 = sb + (kt % STAGES) * STAGE_BYTES;
        #pragma unroll
        for (int ks = 0; ks < 4; ks++) {
            uint32_t ach = (((2 * ks + a_chsel) ^ lxor) << 4);
            uint32_t bch = (((2 * ks + b_chsel) ^ lxor) << 4);
            uint32_t afh[2][4], afl[2][4];
            #pragma unroll
            for (int f = 0; f < 2; f++) {
                ldm4(afh[f][0], afh[f][1], afh[f][2], afh[f][3],
                     s0 + OFF_AH + a_rowb[f] + ach);
                ldm4(afl[f][0], afl[f][1], afl[f][2], afl[f][3],
                     s0 + OFF_AL + a_rowb[f] + ach);
            }
            #pragma unroll
            for (int q = 0; q < 4; q++) {
                uint32_t bh0, bh1, bh2, bh3, bl0, bl1, bl2, bl3;
                ldm4(bh0, bh1, bh2, bh3, s0 + OFF_BH + b_rowb[q] + bch);
                ldm4(bl0, bl1, bl2, bl3, s0 + OFF_BL + b_rowb[q] + bch);
                #pragma unroll
                for (int mf = 0; mf < 2; mf++) {
                    mma16816(acc[mf][2*q],   afh[mf], bh0, bh1);
                    mma16816(acc[mf][2*q],   afh[mf], bl0, bl1);
                    mma16816(acc[mf][2*q],   afl[mf], bh0, bh1);
                    mma16816(acc[mf][2*q+1], afh[mf], bh2, bh3);
                    mma16816(acc[mf][2*q+1], afh[mf], bl2, bl3);
                    mma16816(acc[mf][2*q+1], afl[mf], bh2, bh3);
                }
            }
        }
        __syncthreads();
    }

    // ---- epilogue ----
    const float* bias = bias_g + (size_t)e * NFULL + n0;
    #pragma unroll
    for (int mf = 0; mf < 2; mf++) {
        #pragma unroll
        for (int hh = 0; hh < 2; hh++) {
            int lr = m_warp + mf * 16 + hh * 8 + (lane >> 2);
            int r  = m0 + lr;
            if (r >= cnt) continue;
            if (PHASE == 1) {
                size_t hrow = (size_t)(off + r);
                __half* ph = g_h_hi + hrow * F_ + n0;
                __half* pl = g_h_lo + hrow * F_ + n0;
                #pragma unroll
                for (int nb = 0; nb < 8; nb++) {
                    int col = n_warp + nb * 8 + 2 * (lane & 3);
                    float2 bv = *(const float2*)(bias + col);
                    float v0 = gelu_f(acc[mf][nb][hh*2]     + bv.x);
                    float v1 = gelu_f(acc[mf][nb][hh*2 + 1] + bv.y);
                    __half h0, l0, h1, l1;
                    split_h(v0, h0, l0);
                    split_h(v1, h1, l1);
                    *(uint32_t*)(ph + col) = pack2(h0, h1);
                    *(uint32_t*)(pl + col) = pack2(l0, l1);
                }
            } else {
                int   tok = g_tok[e * N_ + r];
                float gv  = g_gate[e * N_ + r];
                float* orow = out + (size_t)tok * D_ + n0;
                #pragma unroll
                for (int nb = 0; nb < 8; nb++) {
                    int col = n_warp + nb * 8 + 2 * (lane & 3);
                    float2 bv = *(const float2*)(bias + col);
                    atomicAdd(orow + col,     gv * (acc[mf][nb][hh*2]     + bv.x));
                    atomicAdd(orow + col + 1, gv * (acc[mf][nb][hh*2 + 1] + bv.y));
                }
            }
        }
    }
}

// ---------------- launch --------------------------------------------------------
extern "C" void kernel_launch(void* const* d_in, const int* in_sizes, int n_in,
                              void* d_out, int out_size) {
    const float* x  = (const float*)d_in[0];
    const float* gw = (const float*)d_in[1];
    const float* w1 = (const float*)d_in[2];
    const float* b1 = (const float*)d_in[3];
    const float* w2 = (const float*)d_in[4];
    const float* b2 = (const float*)d_in[5];
    float* out = (float*)d_out;

    cudaFuncSetAttribute(moe_gemm_kernel<1>,
                         cudaFuncAttributeMaxDynamicSharedMemorySize, SMEM_TOTAL);
    cudaFuncSetAttribute(moe_gemm_kernel<2>,
                         cudaFuncAttributeMaxDynamicSharedMemorySize, SMEM_TOTAL);

    cudaMemsetAsync(out, 0, (size_t)out_size * sizeof(float), 0);
    init_kernel<<<1, 32>>>();
    gate_kernel<<<(N_ * 32) / 256, 256>>>(x, gw);
    scan_kernel<<<1, 1>>>();

    prep_x_kernel<<<(N_ * (D_ / 4)) / 256, 256>>>(x);
    prep_w_kernel<1><<<dim3(F_/32, D_/32, E_), dim3(32, 8)>>>(w1);
    prep_w_kernel<2><<<dim3(D_/32, F_/32, E_), dim3(32, 8)>>>(w2);

    dim3 g1(F_/BN, N_/BM, E_);     // (32, 64, 8), cnt-guarded
    moe_gemm_kernel<1><<<g1, NTHREADS, SMEM_TOTAL>>>(b1, out);

    dim3 g2(D_/BN, N_/BM, E_);     // (8, 64, 8), cnt-guarded
    moe_gemm_kernel<2><<<g2, NTHREADS, SMEM_TOTAL>>>(b2, out);
}

// round 4
// speedup vs baseline: 4.3972x; 1.3985x over previous
#include <cuda_runtime.h>
#include <cuda_fp16.h>
#include <math.h>
#include <stdint.h>

#define B_ 4
#define T_ 2048
#define D_ 1024
#define E_ 8
#define F_ 4096
#define N_ (B_*T_)            // 8192 tokens

// ---- GEMM tile config ----
#define BM 128
#define BN 128
#define BK 64                 // fp16 elems per k-tile (128 B rows)
#define STAGES 4
#define NTHREADS 256

// smem layout per stage (bytes): A-hi, B-hi, B-lo (activations carry no lo term)
#define OFF_AH 0
#define OFF_BH 16384
#define OFF_BL 32768
#define STAGE_BYTES 49152
#define SMEM_TOTAL (STAGES*STAGE_BYTES)    // 196608

// ---------------- device scratch ---------------------------------------------
__device__ int    g_cnt[E_];
__device__ int    g_tok[E_*N_];
__device__ float  g_gate[E_*N_];
__device__ __half g_x_h[(size_t)N_*D_];
__device__ __half g_w1t_hi[(size_t)E_*F_*D_];   // [E][F][D] K-major
__device__ __half g_w1t_lo[(size_t)E_*F_*D_];
__device__ __half g_w2t_hi[(size_t)E_*D_*F_];   // [E][D][F] K-major
__device__ __half g_w2t_lo[(size_t)E_*D_*F_];
__device__ __half g_h[(size_t)N_*2*F_];         // [N*K][F]

// ---------------- helpers -----------------------------------------------------
__device__ __forceinline__ uint32_t smem_u32(const void* p) {
    uint32_t a;
    asm("{ .reg .u64 t; cvta.to.shared.u64 t, %1; cvt.u32.u64 %0, t; }"
        : "=r"(a) : "l"(p));
    return a;
}
__device__ __forceinline__ void cp16(uint32_t dst, const void* src) {
    asm volatile("cp.async.cg.shared.global [%0], [%1], 16;"
                 :: "r"(dst), "l"(src) : "memory");
}
__device__ __forceinline__ void cp_commit() {
    asm volatile("cp.async.commit_group;" ::: "memory");
}
template<int NN>
__device__ __forceinline__ void cp_wait() {
    asm volatile("cp.async.wait_group %0;" :: "n"(NN) : "memory");
}
__device__ __forceinline__ void ldm4(uint32_t& r0, uint32_t& r1,
                                     uint32_t& r2, uint32_t& r3, uint32_t a) {
    asm volatile("ldmatrix.sync.aligned.m8n8.x4.shared.b16 {%0,%1,%2,%3}, [%4];"
                 : "=r"(r0), "=r"(r1), "=r"(r2), "=r"(r3) : "r"(a));
}
__device__ __forceinline__ void mma16816(float* c, const uint32_t* a,
                                         uint32_t b0, uint32_t b1) {
    asm volatile(
        "mma.sync.aligned.m16n8k16.row.col.f32.f16.f16.f32 "
        "{%0,%1,%2,%3}, {%4,%5,%6,%7}, {%8,%9}, {%0,%1,%2,%3};"
        : "+f"(c[0]), "+f"(c[1]), "+f"(c[2]), "+f"(c[3])
        : "r"(a[0]), "r"(a[1]), "r"(a[2]), "r"(a[3]), "r"(b0), "r"(b1));
}
__device__ __forceinline__ void split_h(float v, __half& h, __half& l) {
    h = __float2half_rn(v);
    l = __float2half_rn(v - __half2float(h));
}
__device__ __forceinline__ uint32_t pack2(__half a, __half b) {
    return (uint32_t)__half_as_ushort(a) | ((uint32_t)__half_as_ushort(b) << 16);
}
__device__ __forceinline__ float gelu_f(float v) {
    return 0.5f * v * (1.f + erff(v * 0.70710678118654752440f));
}

// ---------------- fused prep: x->fp16, w1/w2 transpose+split ------------------
#define XBLKS (N_*D_/4/NTHREADS)        // 8192
#define W1BLKS ((F_/32)*(D_/32)*E_)     // 32768
#define W2BLKS ((D_/32)*(F_/32)*E_)     // 32768

__global__ void prep_all_kernel(const float* __restrict__ x,
                                const float* __restrict__ w1,
                                const float* __restrict__ w2) {
    int bb  = blockIdx.x;
    int tid = threadIdx.x;
    if (bb < XBLKS) {
        size_t i4 = (size_t)bb * NTHREADS + tid;
        float4 v = ((const float4*)x)[i4];
        ((uint2*)g_x_h)[i4] = make_uint2(
            pack2(__float2half_rn(v.x), __float2half_rn(v.y)),
            pack2(__float2half_rn(v.z), __float2half_rn(v.w)));
        return;
    }
    __shared__ float tile[32][33];
    int tx = tid & 31, ty = tid >> 5;          // (32, 8)
    const float* w; __half* whi; __half* wlo;
    int RIN, CIN, bid;
    if (bb < XBLKS + W1BLKS) {
        bid = bb - XBLKS; w = w1; whi = g_w1t_hi; wlo = g_w1t_lo;
        RIN = D_; CIN = F_;
    } else {
        bid = bb - XBLKS - W1BLKS; w = w2; whi = g_w2t_hi; wlo = g_w2t_lo;
        RIN = F_; CIN = D_;
    }
    int cb = CIN / 32, rb = RIN / 32;
    int e   = bid / (cb * rb);
    int rem = bid % (cb * rb);
    int c0  = (rem % cb) * 32, r0 = (rem / cb) * 32;
    const float* wi = w + (size_t)e * RIN * CIN;
    #pragma unroll
    for (int i = 0; i < 4; i++)
        tile[ty + 8*i][tx] = wi[(size_t)(r0 + ty + 8*i) * CIN + c0 + tx];
    __syncthreads();
    size_t ob = (size_t)e * CIN * RIN;
    #pragma unroll
    for (int i = 0; i < 4; i++) {
        int c = c0 + ty + 8*i, r = r0 + tx;
        __half h, l;
        split_h(tile[tx][ty + 8*i], h, l);
        whi[ob + (size_t)c * RIN + r] = h;
        wlo[ob + (size_t)c * RIN + r] = l;
    }
}

// ---------------- gating ------------------------------------------------------
__global__ void init_kernel() { if (threadIdx.x < E_) g_cnt[threadIdx.x] = 0; }

__global__ void gate_kernel(const float* __restrict__ x,
                            const float* __restrict__ gw) {
    int gtid = blockIdx.x * blockDim.x + threadIdx.x;
    int t = gtid >> 5, lane = gtid & 31;
    if (t >= N_) return;
    const float* xr = x + (size_t)t * D_;
    float acc[E_];
    #pragma unroll
    for (int e = 0; e < E_; e++) acc[e] = 0.f;
    for (int d = lane; d < D_; d += 32) {
        float xv = xr[d];
        #pragma unroll
        for (int e = 0; e < E_; e++) acc[e] = fmaf(xv, gw[d * E_ + e], acc[e]);
    }
    #pragma unroll
    for (int e = 0; e < E_; e++)
        #pragma unroll
        for (int o = 16; o > 0; o >>= 1)
            acc[e] += __shfl_xor_sync(0xffffffffu, acc[e], o);
    if (lane == 0) {
        int i0 = 0; float v0 = acc[0];
        #pragma unroll
        for (int e = 1; e < E_; e++) if (acc[e] > v0) { v0 = acc[e]; i0 = e; }
        int i1 = -1; float v1 = -1e30f;
        #pragma unroll
        for (int e = 0; e < E_; e++) if (e != i0 && acc[e] > v1) { v1 = acc[e]; i1 = e; }
        float e1 = expf(v1 - v0), inv = 1.f / (1.f + e1);
        int p0 = atomicAdd(&g_cnt[i0], 1);
        g_tok[i0 * N_ + p0] = t;  g_gate[i0 * N_ + p0] = inv;
        int p1 = atomicAdd(&g_cnt[i1], 1);
        g_tok[i1 * N_ + p1] = t;  g_gate[i1 * N_ + p1] = e1 * inv;
    }
}

// ---------------- grouped GEMM on HMMA (2-term split: Ah*Bh + Ah*Bl) ----------
// PHASE 1: h = gelu(gather(x_h) @ w1t[e]^T + b1[e])
// PHASE 2: out += gate * (h @ w2t[e]^T + b2[e])
template<int PHASE>
__global__ __launch_bounds__(NTHREADS, 1)
void moe_gemm_kernel(const float* __restrict__ bias_g, float* __restrict__ out) {
    constexpr int KT    = (PHASE == 1) ? D_ : F_;
    constexpr int KT64  = KT / BK;
    constexpr int NFULL = (PHASE == 1) ? F_ : D_;

    int e   = blockIdx.z;
    int cnt = g_cnt[e];
    int m0  = blockIdx.y * BM;
    if (m0 >= cnt) return;
    int n0  = blockIdx.x * BN;
    int off = 0;                       // in-kernel exclusive scan (8 reads)
    #pragma unroll
    for (int j = 0; j < E_; j++) if (j < e) off += g_cnt[j];

    extern __shared__ __align__(1024) char smem[];
    uint32_t sb = smem_u32(smem);
    int tid = threadIdx.x, wid = tid >> 5, lane = tid & 31;

    const __half* Ah = (PHASE == 1) ? g_x_h : g_h;
    const __half* Bh = ((PHASE == 1) ? g_w1t_hi : g_w2t_hi) + (size_t)e * (size_t)NFULL * KT;
    const __half* Bl = ((PHASE == 1) ? g_w1t_lo : g_w2t_lo) + (size_t)e * (size_t)NFULL * KT;

    // ---- per-thread cp.async setup: 4 rows per tile, fixed chunk = tid&7 ----
    int rbase = tid >> 3;
    int csw   = (tid & 7) ^ (rbase & 7);
    const __half *a_p[4], *b_h[4], *b_l[4];
    uint32_t dstoff[4];
    #pragma unroll
    for (int i = 0; i < 4; i++) {
        int r = rbase + 32 * i;
        dstoff[i] = (uint32_t)(r * 128 + csw * 16);
        int grow = min(m0 + r, cnt - 1);
        size_t arow = (PHASE == 1) ? (size_t)g_tok[e * N_ + grow]
                                   : (size_t)(off + grow);
        a_p[i] = Ah + arow * KT + (tid & 7) * 8;
        size_t brow = (size_t)(n0 + r);
        b_h[i] = Bh + brow * KT + (tid & 7) * 8;
        b_l[i] = Bl + brow * KT + (tid & 7) * 8;
    }

    auto load_stage = [&](int kt, int slot) {
        uint32_t s0 = sb + slot * STAGE_BYTES;
        int koff = kt * BK;
        #pragma unroll
        for (int i = 0; i < 4; i++) {
            cp16(s0 + OFF_AH + dstoff[i], a_p[i] + koff);
            cp16(s0 + OFF_BH + dstoff[i], b_h[i] + koff);
            cp16(s0 + OFF_BL + dstoff[i], b_l[i] + koff);
        }
    };

    // ---- fragment address constants ----
    int m_warp = (wid & 3) * 32;
    int n_warp = (wid >> 2) * 64;
    uint32_t a_rowb[2], b_rowb[4];
    #pragma unroll
    for (int f = 0; f < 2; f++)
        a_rowb[f] = (uint32_t)((m_warp + f * 16 + (lane & 15)) * 128);
    #pragma unroll
    for (int q = 0; q < 4; q++)
        b_rowb[q] = (uint32_t)((n_warp + q * 16 + ((lane & 16) >> 1) + (lane & 7)) * 128);
    uint32_t a_chsel = (uint32_t)(lane >> 4);
    uint32_t b_chsel = (uint32_t)((lane >> 3) & 1);
    uint32_t lxor    = (uint32_t)(lane & 7);

    float acc[2][8][4];
    #pragma unroll
    for (int mf = 0; mf < 2; mf++)
        #pragma unroll
        for (int nb = 0; nb < 8; nb++)
            #pragma unroll
            for (int i = 0; i < 4; i++) acc[mf][nb][i] = 0.f;

    // ---- prologue: fill STAGES-1 slots ----
    #pragma unroll
    for (int p = 0; p < STAGES - 1; p++) {
        if (p < KT64) load_stage(p, p);
        cp_commit();
    }

    // ---- main loop ----
    for (int kt = 0; kt < KT64; kt++) {
        cp_wait<STAGES - 2>();
        __syncthreads();
        if (kt + STAGES - 1 < KT64)
            load_stage(kt + STAGES - 1, (kt + STAGES - 1) % STAGES);
        cp_commit();

        uint32_t s0 = sb + (kt % STAGES) * STAGE_BYTES;
        #pragma unroll
        for (int ks = 0; ks < 4; ks++) {
            uint32_t ach = (((2 * ks + a_chsel) ^ lxor) << 4);
            uint32_t bch = (((2 * ks + b_chsel) ^ lxor) << 4);
            uint32_t af[2][4];
            #pragma unroll
            for (int f = 0; f < 2; f++)
                ldm4(af[f][0], af[f][1], af[f][2], af[f][3],
                     s0 + OFF_AH + a_rowb[f] + ach);
            #pragma unroll
            for (int q = 0; q < 4; q++) {
                uint32_t bh0, bh1, bh2, bh3, bl0, bl1, bl2, bl3;
                ldm4(bh0, bh1, bh2, bh3, s0 + OFF_BH + b_rowb[q] + bch);
                ldm4(bl0, bl1, bl2, bl3, s0 + OFF_BL + b_rowb[q] + bch);
                #pragma unroll
                for (int mf = 0; mf < 2; mf++) {
                    mma16816(acc[mf][2*q],   af[mf], bh0, bh1);
                    mma16816(acc[mf][2*q],   af[mf], bl0, bl1);
                    mma16816(acc[mf][2*q+1], af[mf], bh2, bh3);
                    mma16816(acc[mf][2*q+1], af[mf], bl2, bl3);
                }
            }
        }
        __syncthreads();
    }

    // ---- epilogue ----
    const float* bias = bias_g + (size_t)e * NFULL + n0;
    #pragma unroll
    for (int mf = 0; mf < 2; mf++) {
        #pragma unroll
        for (int hh = 0; hh < 2; hh++) {
            int lr = m_warp + mf * 16 + hh * 8 + (lane >> 2);
            int r  = m0 + lr;
            if (r >= cnt) continue;
            if (PHASE == 1) {
                __half* ph = g_h + (size_t)(off + r) * F_ + n0;
                #pragma unroll
                for (int nb = 0; nb < 8; nb++) {
                    int col = n_warp + nb * 8 + 2 * (lane & 3);
                    float2 bv = *(const float2*)(bias + col);
                    float v0 = gelu_f(acc[mf][nb][hh*2]     + bv.x);
                    float v1 = gelu_f(acc[mf][nb][hh*2 + 1] + bv.y);
                    *(uint32_t*)(ph + col) =
                        pack2(__float2half_rn(v0), __float2half_rn(v1));
                }
            } else {
                int   tok = g_tok[e * N_ + r];
                float gv  = g_gate[e * N_ + r];
                float* orow = out + (size_t)tok * D_ + n0;
                #pragma unroll
                for (int nb = 0; nb < 8; nb++) {
                    int col = n_warp + nb * 8 + 2 * (lane & 3);
                    float2 bv = *(const float2*)(bias + col);
                    atomicAdd(orow + col,     gv * (acc[mf][nb][hh*2]     + bv.x));
                    atomicAdd(orow + col + 1, gv * (acc[mf][nb][hh*2 + 1] + bv.y));
                }
            }
        }
    }
}

// ---------------- launch --------------------------------------------------------
extern "C" void kernel_launch(void* const* d_in, const int* in_sizes, int n_in,
                              void* d_out, int out_size) {
    const float* x  = (const float*)d_in[0];
    const float* gw = (const float*)d_in[1];
    const float* w1 = (const float*)d_in[2];
    const float* b1 = (const float*)d_in[3];
    const float* w2 = (const float*)d_in[4];
    const float* b2 = (const float*)d_in[5];
    float* out = (float*)d_out;

    cudaFuncSetAttribute(moe_gemm_kernel<1>,
                         cudaFuncAttributeMaxDynamicSharedMemorySize, SMEM_TOTAL);
    cudaFuncSetAttribute(moe_gemm_kernel<2>,
                         cudaFuncAttributeMaxDynamicSharedMemorySize, SMEM_TOTAL);

    cudaMemsetAsync(out, 0, (size_t)out_size * sizeof(float), 0);
    prep_all_kernel<<<XBLKS + W1BLKS + W2BLKS, NTHREADS>>>(x, w1, w2);
    init_kernel<<<1, 32>>>();
    gate_kernel<<<(N_ * 32) / 256, 256>>>(x, gw);

    dim3 g1(F_/BN, N_/BM, E_);     // (32, 64, 8), cnt-guarded
    moe_gemm_kernel<1><<<g1, NTHREADS, SMEM_TOTAL>>>(b1, out);

    dim3 g2(D_/BN, N_/BM, E_);     // (8, 64, 8), cnt-guarded
    moe_gemm_kernel<2><<<g2, NTHREADS, SMEM_TOTAL>>>(b2, out);
}